// round 10
// baseline (speedup 1.0000x reference)
#include <cuda_runtime.h>
#include <cuda_bf16.h>

#define Bn 8
#define Dn 1024
#define Gn 32
#define Kn 64
#define NPn 1024
#define NTILE 128     // n-rows per work unit
#define KC 32         // k-chunk (pipeline stage = half a group)
#define GRID 296      // 148 SMs * 2 CTA/SM -> exactly one wave
#define THREADS 512

// Scratch (device globals; no allocation allowed)
__device__ float g_xzT[(size_t)Bn * Dn * NPn];   // 32 MB: z transposed [b][d][n]
__device__ int   g_items[Bn * Gn];               // packed (b<<8)|g, valid groups
__device__ int   g_nitems;

// packed dual-fp32 FMA (Blackwell f32x2; PTX-only, ptxas won't auto-fuse)
#define FMA2(acc, m, r) \
    asm("fma.rn.f32x2 %0, %1, %2, %0;" : "+l"(acc) : "l"(m), "l"(r))

#define CP_ASYNC16(dst_s32, src_g) \
    asm volatile("cp.async.cg.shared.global [%0], [%1], 16;" \
                 :: "r"(dst_s32), "l"(src_g))
#define CP_COMMIT() asm volatile("cp.async.commit_group;")

// ---------------------------------------------------------------------------
// Kernel 1 (prep): lean tiled transpose + out zeroing + work-list build.
// ---------------------------------------------------------------------------
__global__ void prep_kernel(const float* __restrict__ x,
                            const float* __restrict__ xopt,
                            const int*   __restrict__ gc,
                            float*       __restrict__ out)
{
    __shared__ float t[32][33];
    int b  = blockIdx.z;
    int n0 = blockIdx.x * 32;
    int d0 = blockIdx.y * 32;
    int tx = threadIdx.x, ty = threadIdx.y;

    #pragma unroll
    for (int j = ty; j < 32; j += 8) {
        int n = n0 + j, d = d0 + tx;
        t[j][tx] = x[((size_t)b * NPn + n) * Dn + d] - xopt[b * Dn + d];
    }
    __syncthreads();
    #pragma unroll
    for (int j = ty; j < 32; j += 8) {
        int d = d0 + j, n = n0 + tx;
        g_xzT[((size_t)b * Dn + d) * NPn + n] = t[tx][j];
    }

    if (blockIdx.x == 0 && blockIdx.y == 0) {
        int tid = ty * 32 + tx;
        for (int i = tid; i < NPn; i += 256) out[b * NPn + i] = 0.0f;
        if (b == 0 && tid == 0) {
            int m = 0;
            for (int bb = 0; bb < Bn; ++bb) {
                int c = gc[bb];
                for (int g = 0; g < c; ++g) g_items[m++] = (bb << 8) | g;
            }
            g_nitems = m;
        }
    }
}

// ---------------------------------------------------------------------------
// Kernel 2: fitness. Grid GRID=296 (one wave @ 2 CTA/SM), block 512.
// CTA c processes units c, c+GRID, ... ; unit = item*8 + tile.
// Stage = 32-k half of one unit; double-buffered, ONE barrier per stage.
// Thread tile 4n x 4l over 16 warps (16*4 = 64 l):
//   nt = tid&31 -> n quad (4*nt),  lt = tid>>5 (0..15) -> l quad (4*lt).
// Per-kl body: 1 LDS.128 z + 1 broadcast LDS.128 R + 4 MOV dup + 8 FMA2.
// 8 warps/SMSP -> fma-bound (demand 128 cyc vs 112 issue slots per round).
// Dynamic smem: Rs (16KB) | zs[2] (32KB) | cf (256B) = 48.4 KB.
// ---------------------------------------------------------------------------
__global__ __launch_bounds__(THREADS, 2) void fitness_kernel(
    const float* __restrict__ R,
    const int*   __restrict__ gidx,
    const void*  __restrict__ vm,
    const float* __restrict__ w,
    float*       __restrict__ out)
{
    extern __shared__ char sm[];
    float* Rs   = (float*)sm;                        // 16 KB
    float* zs   = (float*)(sm + 16384);              // 2 * 16 KB
    float* cf_s = (float*)(sm + 16384 + 32768);      // 256 B

    int tid = threadIdx.x;
    int cta = blockIdx.x;
    int nt  = tid & 31;
    int lt  = tid >> 5;          // 0..15 -> l quad

    int nunits = 8 * g_nitems;
    int mu = (cta < nunits) ? ((nunits - 1 - cta) / GRID + 1) : 0;
    if (mu == 0) return;
    int ts = 2 * mu;

    // valid_mask storage-width detect (uniform across threads)
    int mode4 = 1;
    #pragma unroll
    for (int i = 0; i < 16; ++i) {
        unsigned int v = __ldg((const unsigned int*)vm + i);
        if (v != 0u && v != 1u && v != 0x3F800000u) mode4 = 0;
    }

    for (int i = tid; i < Kn * Kn; i += THREADS) Rs[i] = R[i];
    if (tid < Kn) cf_s[tid] = exp2f((float)tid * (19.931568569324174f / 63.0f));
    __syncthreads();   // Rs/cf_s visible to all warps before any use

    // gather: thread owns k_local = tid>>4 (0..31), 16B n-chunks (tid&15)+16j
    int kq = tid >> 4;
    int nq = tid & 15;
    unsigned int zb0 = (unsigned int)__cvta_generic_to_shared(zs);

    // stage j: unit = cta + (j>>1)*GRID, half = j&1
    #define ISSUE(j)                                                           \
    {                                                                          \
        int u_  = cta + ((j) >> 1) * GRID;                                     \
        int it_ = g_items[u_ >> 3];                                            \
        int b_  = it_ >> 8, g_ = it_ & 255, n0_ = (u_ & 7) * NTILE;            \
        int k_  = ((j) & 1) * KC + kq;                                         \
        int col_ = __ldg(gidx + (b_ * Gn + g_) * Kn + k_);                     \
        const float* src_ = &g_xzT[((size_t)(b_ * Dn + col_)) * NPn + n0_];    \
        unsigned int db_ = zb0 + ((j) & 1) * 16384 + kq * (NTILE * 4);         \
        _Pragma("unroll")                                                      \
        for (int jj = 0; jj < 2; ++jj) {                                       \
            int nof_ = (nq + 16 * jj) * 4;                                     \
            CP_ASYNC16(db_ + nof_ * 4, src_ + nof_);                           \
        }                                                                      \
        CP_COMMIT();                                                           \
    }

    float cw_r[4];
    unsigned long long acc[4][2];     // [l within quad][n-pair]
    int ub = 0, un0 = 0;

    ISSUE(0);

    for (int j = 0; j < ts; ++j) {
        int h = j & 1;

        asm volatile("cp.async.wait_group 0;");   // stage j landed (only pending)
        __syncthreads();   // data visible; all warps past compute(j-1)
                           // -> buffer (j+1)&1 free to overwrite
        if (j + 1 < ts) ISSUE(j + 1);

        if (h == 0) {
            // new unit: decode + cw LDGs (consumed only at h==1), reset accs
            int u  = cta + (j >> 1) * GRID;
            int it = g_items[u >> 3];
            ub  = it >> 8;
            un0 = (u & 7) * NTILE;
            int g = it & 255;
            float wv = __ldg(w + ub * Gn + g);
            int base = (ub * Gn + g) * Kn + lt * 4;
            #pragma unroll
            for (int jj = 0; jj < 4; ++jj) {
                bool m;
                if (mode4) m = (__ldg((const unsigned int*)vm + base + jj) != 0u);
                else       m = (__ldg((const unsigned char*)vm + base + jj) != 0);
                cw_r[jj] = m ? cf_s[lt * 4 + jj] * wv : 0.0f;
            }
            #pragma unroll
            for (int i = 0; i < 4; ++i) { acc[i][0] = 0ull; acc[i][1] = 0ull; }
        }

        const float* zb   = zs + (j & 1) * (KC * NTILE);
        const float* rrow = &Rs[h * KC * Kn + lt * 4];

        #pragma unroll 8
        for (int kl = 0; kl < KC; ++kl) {
            // z: one LDS.128 = two u64 n-pairs (natively packed)
            ulonglong2 zp = *(const ulonglong2*)&zb[kl * NTILE + nt * 4];
            // R: one broadcast LDS.128 = 4 l-values, dup into {r,r} pairs
            float4 r4 = *(const float4*)&rrow[kl * Kn];
            unsigned long long rr[4];
            asm("mov.b64 %0, {%1, %1};" : "=l"(rr[0]) : "f"(r4.x));
            asm("mov.b64 %0, {%1, %1};" : "=l"(rr[1]) : "f"(r4.y));
            asm("mov.b64 %0, {%1, %1};" : "=l"(rr[2]) : "f"(r4.z));
            asm("mov.b64 %0, {%1, %1};" : "=l"(rr[3]) : "f"(r4.w));
            #pragma unroll
            for (int i = 0; i < 4; ++i) {
                FMA2(acc[i][0], zp.x, rr[i]);
                FMA2(acc[i][1], zp.y, rr[i]);
            }
        }

        if (h == 1) {
            // unit done: fold squares with cw, reduce straight to gmem (RED)
            float fs[4] = {0.0f, 0.0f, 0.0f, 0.0f};
            #pragma unroll
            for (int l = 0; l < 4; ++l) {
                #pragma unroll
                for (int p = 0; p < 2; ++p) {
                    float lo = __uint_as_float((unsigned int)(acc[l][p] & 0xFFFFFFFFull));
                    float hi = __uint_as_float((unsigned int)(acc[l][p] >> 32));
                    fs[2 * p]     += cw_r[l] * lo * lo;
                    fs[2 * p + 1] += cw_r[l] * hi * hi;
                }
            }
            #pragma unroll
            for (int i = 0; i < 4; ++i)
                atomicAdd(&out[ub * NPn + un0 + nt * 4 + i], fs[i]);
        }
    }
    #undef ISSUE
}

// ---------------------------------------------------------------------------
// kernel_launch
// Inputs (metadata order): x, weights, xopt, R, group_indices, valid_mask,
//                          group_counts
// ---------------------------------------------------------------------------
extern "C" void kernel_launch(void* const* d_in, const int* in_sizes, int n_in,
                              void* d_out, int out_size)
{
    const float* x      = (const float*)d_in[0];
    const float* w      = (const float*)d_in[1];
    const float* xopt   = (const float*)d_in[2];
    const float* R      = (const float*)d_in[3];
    const int*   gidx   = (const int*)d_in[4];
    const void*  vmask  = (const void*)d_in[5];
    const int*   gc     = (const int*)d_in[6];
    float*       out    = (float*)d_out;

    const int smem_bytes = 16384 + 32768 + 256;
    cudaFuncSetAttribute(fitness_kernel,
                         cudaFuncAttributeMaxDynamicSharedMemorySize, smem_bytes);

    dim3 tg(NPn / 32, Dn / 32, Bn);
    prep_kernel<<<tg, dim3(32, 8)>>>(x, xopt, gc, out);

    fitness_kernel<<<GRID, THREADS, smem_bytes>>>(R, gidx, vmask, w, out);
}

// round 11
// speedup vs baseline: 1.4404x; 1.4404x over previous
#include <cuda_runtime.h>
#include <cuda_bf16.h>

#define Bn 8
#define Dn 1024
#define Gn 32
#define Kn 64
#define NPn 1024
#define NTILE 128     // n-rows per work unit
#define KC 32         // k-chunk (pipeline stage = half a group)
#define GRID 592      // 148 SMs * 4 CTA/SM -> exactly one wave

// Scratch (device globals; no allocation allowed)
__device__ float g_xzT[(size_t)Bn * Dn * NPn];   // 32 MB: z transposed [b][d][n]
__device__ float g_cw[Bn * Gn * Kn];             // folded coeff*mask*weight
__device__ int   g_items[Bn * Gn];               // packed (b<<8)|g, valid groups
__device__ int   g_nitems;

// packed dual-fp32 FMA (Blackwell f32x2; PTX-only, ptxas won't auto-fuse)
#define FMA2(acc, m, r) \
    asm("fma.rn.f32x2 %0, %1, %2, %0;" : "+l"(acc) : "l"(m), "l"(r))

#define CP_ASYNC16(dst_s32, src_g) \
    asm volatile("cp.async.cg.shared.global [%0], [%1], 16;" \
                 :: "r"(dst_s32), "l"(src_g))
#define CP_COMMIT() asm volatile("cp.async.commit_group;")

// ---------------------------------------------------------------------------
// Kernel 1 (prep): lean tiled transpose; blocks (0,0,b) also build cw
// (exp2f only — fp32 MUFU, no register poison), out zeroing, work list.
// ---------------------------------------------------------------------------
__global__ void prep_kernel(const float* __restrict__ x,
                            const float* __restrict__ xopt,
                            const int*   __restrict__ gc,
                            const void*  __restrict__ vm,
                            const float* __restrict__ w,
                            float*       __restrict__ out)
{
    __shared__ float t[32][33];
    int b  = blockIdx.z;
    int n0 = blockIdx.x * 32;
    int d0 = blockIdx.y * 32;
    int tx = threadIdx.x, ty = threadIdx.y;

    #pragma unroll
    for (int j = ty; j < 32; j += 8) {
        int n = n0 + j, d = d0 + tx;
        t[j][tx] = x[((size_t)b * NPn + n) * Dn + d] - xopt[b * Dn + d];
    }
    __syncthreads();
    #pragma unroll
    for (int j = ty; j < 32; j += 8) {
        int d = d0 + j, n = n0 + tx;
        g_xzT[((size_t)b * Dn + d) * NPn + n] = t[tx][j];
    }

    if (blockIdx.x == 0 && blockIdx.y == 0) {
        int tid = ty * 32 + tx;

        // valid_mask storage width (uniform, 16 L2 loads)
        int mode4 = 1;
        #pragma unroll
        for (int i = 0; i < 16; ++i) {
            unsigned int v = __ldg((const unsigned int*)vm + i);
            if (v != 0u && v != 1u && v != 0x3F800000u) mode4 = 0;
        }

        int gcb = gc[b];
        for (int i = tid; i < Gn * Kn; i += 256) {
            int g = i >> 6, k = i & 63;
            int gi = b * Gn * Kn + i;
            bool m;
            if (mode4) m = (((const unsigned int*)vm)[gi] != 0u);
            else       m = (((const unsigned char*)vm)[gi] != 0);
            float cf = exp2f((float)k * (19.931568569324174f / 63.0f));
            float wv = (g < gcb) ? w[b * Gn + g] : 0.0f;
            g_cw[gi] = m ? cf * wv : 0.0f;
        }
        for (int i = tid; i < NPn; i += 256) out[b * NPn + i] = 0.0f;
        if (b == 0 && tid == 0) {
            int mcnt = 0;
            for (int bb = 0; bb < Bn; ++bb) {
                int c = gc[bb];
                for (int g = 0; g < c; ++g) g_items[mcnt++] = (bb << 8) | g;
            }
            g_nitems = mcnt;
        }
    }
}

// ---------------------------------------------------------------------------
// Kernel 2: fitness. Grid GRID=592 (one wave @ 4 CTA/SM), block 256.
// CTA c processes units c, c+GRID, ... ; unit = item*8 + tile.
// Stage = 32-k half of one unit; DOUBLE-buffered, one barrier per stage
// (xzT is L2-resident, depth-1 prefetch suffices).
// Thread tile 4n x 8l (R7 body: 1 LDS.128 z + 2 bcast LDS.128 R + 4 MOV dup
// + 16 FMA2 — best z-bytes/FMA ratio found).
// cw loaded from g_cw only at fold time (once per unit, L2-hot).
// Dynamic smem: Rs (16KB) | zs[2] (32KB) = 48.1 KB.
// ---------------------------------------------------------------------------
__global__ __launch_bounds__(256, 4) void fitness_kernel(
    const float* __restrict__ R,
    const int*   __restrict__ gidx,
    float*       __restrict__ out)
{
    extern __shared__ char sm[];
    float* Rs = (float*)sm;                 // 16 KB
    float* zs = (float*)(sm + 16384);       // 2 * 16 KB

    int tid = threadIdx.x;
    int cta = blockIdx.x;
    int nt  = tid & 31;
    int lt  = tid >> 5;

    int nunits = 8 * g_nitems;
    int mu = (cta < nunits) ? ((nunits - 1 - cta) / GRID + 1) : 0;
    if (mu == 0) return;
    int ts = 2 * mu;

    for (int i = tid; i < Kn * Kn; i += 256) Rs[i] = R[i];
    __syncthreads();   // Rs visible to all warps before any use

    // gather: thread owns k_local = tid>>3 (0..31), 16B n-chunks (tid&7)+8j
    int kq = tid >> 3;
    int nq = tid & 7;
    unsigned int zb0 = (unsigned int)__cvta_generic_to_shared(zs);

    // stage j: unit = cta + (j>>1)*GRID, half = j&1
    #define ISSUE(j)                                                           \
    {                                                                          \
        int u_  = cta + ((j) >> 1) * GRID;                                     \
        int it_ = g_items[u_ >> 3];                                            \
        int b_  = it_ >> 8, g_ = it_ & 255, n0_ = (u_ & 7) * NTILE;            \
        int k_  = ((j) & 1) * KC + kq;                                         \
        int col_ = __ldg(gidx + (b_ * Gn + g_) * Kn + k_);                     \
        const float* src_ = &g_xzT[((size_t)(b_ * Dn + col_)) * NPn + n0_];    \
        unsigned int db_ = zb0 + ((j) & 1) * 16384 + kq * (NTILE * 4);         \
        _Pragma("unroll")                                                      \
        for (int jj = 0; jj < 4; ++jj) {                                       \
            int nof_ = (nq + 8 * jj) * 4;                                      \
            CP_ASYNC16(db_ + nof_ * 4, src_ + nof_);                           \
        }                                                                      \
        CP_COMMIT();                                                           \
    }

    unsigned long long acc[4][4];   // [n][l-pair]
    int uitem = 0, un0 = 0;

    ISSUE(0);

    for (int j = 0; j < ts; ++j) {
        int h = j & 1;

        asm volatile("cp.async.wait_group 0;");   // stage j landed
        __syncthreads();   // data visible; all warps past compute(j-1)
                           // -> buffer (j+1)&1 free to overwrite
        if (j + 1 < ts) ISSUE(j + 1);

        if (h == 0) {
            // new unit: decode, reset accumulators
            int u = cta + (j >> 1) * GRID;
            uitem = u >> 3;
            un0   = (u & 7) * NTILE;
            #pragma unroll
            for (int i = 0; i < 4; ++i)
                #pragma unroll
                for (int jj = 0; jj < 4; ++jj) acc[i][jj] = 0ull;
        }

        const float* zb   = zs + (j & 1) * (KC * NTILE);
        const float* rrow = &Rs[h * KC * Kn + lt * 8];

        #pragma unroll 8
        for (int kl = 0; kl < KC; ++kl) {
            float4 z4 = *(const float4*)&zb[kl * NTILE + nt * 4];
            const ulonglong2* rp = (const ulonglong2*)&rrow[kl * Kn];
            ulonglong2 ra = rp[0];
            ulonglong2 rb = rp[1];
            unsigned long long z2[4];
            asm("mov.b64 %0, {%1, %1};" : "=l"(z2[0]) : "f"(z4.x));
            asm("mov.b64 %0, {%1, %1};" : "=l"(z2[1]) : "f"(z4.y));
            asm("mov.b64 %0, {%1, %1};" : "=l"(z2[2]) : "f"(z4.z));
            asm("mov.b64 %0, {%1, %1};" : "=l"(z2[3]) : "f"(z4.w));
            #pragma unroll
            for (int i = 0; i < 4; ++i) {
                FMA2(acc[i][0], z2[i], ra.x);
                FMA2(acc[i][1], z2[i], ra.y);
                FMA2(acc[i][2], z2[i], rb.x);
                FMA2(acc[i][3], z2[i], rb.y);
            }
        }

        if (h == 1) {
            // unit done: load folded cw (2x LDG.128, L2-hot, once per unit),
            // square-fold, reduce straight to gmem
            int it = g_items[uitem];
            int bb = it >> 8, gg = it & 255;
            const float4* cwp =
                (const float4*)(g_cw + (bb * Gn + gg) * Kn + lt * 8);
            float4 c0 = __ldg(cwp);
            float4 c1 = __ldg(cwp + 1);
            float cw_r[8] = {c0.x, c0.y, c0.z, c0.w, c1.x, c1.y, c1.z, c1.w};

            #pragma unroll
            for (int i = 0; i < 4; ++i) {
                float s0 = 0.0f;
                #pragma unroll
                for (int jj = 0; jj < 4; ++jj) {
                    float lo = __uint_as_float((unsigned int)(acc[i][jj] & 0xFFFFFFFFull));
                    float hi = __uint_as_float((unsigned int)(acc[i][jj] >> 32));
                    s0 += cw_r[2 * jj] * lo * lo + cw_r[2 * jj + 1] * hi * hi;
                }
                atomicAdd(&out[bb * NPn + un0 + nt * 4 + i], s0);
            }
        }
    }
    #undef ISSUE
}

// ---------------------------------------------------------------------------
// kernel_launch
// Inputs (metadata order): x, weights, xopt, R, group_indices, valid_mask,
//                          group_counts
// ---------------------------------------------------------------------------
extern "C" void kernel_launch(void* const* d_in, const int* in_sizes, int n_in,
                              void* d_out, int out_size)
{
    const float* x      = (const float*)d_in[0];
    const float* w      = (const float*)d_in[1];
    const float* xopt   = (const float*)d_in[2];
    const float* R      = (const float*)d_in[3];
    const int*   gidx   = (const int*)d_in[4];
    const void*  vmask  = (const void*)d_in[5];
    const int*   gc     = (const int*)d_in[6];
    float*       out    = (float*)d_out;

    const int smem_bytes = 16384 + 32768;
    cudaFuncSetAttribute(fitness_kernel,
                         cudaFuncAttributeMaxDynamicSharedMemorySize, smem_bytes);

    dim3 tg(NPn / 32, Dn / 32, Bn);
    prep_kernel<<<tg, dim3(32, 8)>>>(x, xopt, gc, vmask, w, out);

    fitness_kernel<<<GRID, 256, smem_bytes>>>(R, gidx, out);
}